// round 15
// baseline (speedup 1.0000x reference)
#include <cuda_runtime.h>
#include <cuda_bf16.h>
#include <cstdint>

#define Nn 100000
#define Ee 3200000
#define Bb 64
#define FIN 64
#define EIN 16
#define ADIM 13
#define Hh 32
#define OUT 64
#define EPS_GEN 1e-7f
#define EPS_BN 1e-5f

// ---------------- scratch (device globals; no allocs allowed) ----------------
__device__ float  g_h[Nn * Hh];        // node encoder output [N,32]
__device__ float  g_esum[Nn * Hh];     // sum of exp(msg) per dst
__device__ float  g_wsum[Nn * Hh];     // sum of msg*exp(msg) per dst
__device__ float  g_y1[Nn * OUT];
__device__ float  g_y2[Nn * OUT];
__device__ float  g_y3[Nn * OUT];
__device__ double g_stats[3 * 128];    // per stage: [sum(64) | sumsq(64)]
__device__ float  g_pool[Bb * OUT];
__device__ float  g_cnt[Bb];

// ---------------- helpers ----------------
__device__ __forceinline__ void red_add_v4(float* addr, float4 v) {
    asm volatile("red.global.add.v4.f32 [%0], {%1,%2,%3,%4};"
                 :: "l"(addr), "f"(v.x), "f"(v.y), "f"(v.z), "f"(v.w) : "memory");
}

__device__ __forceinline__ void red_add_v2(float* addr, float2 v) {
    asm volatile("red.global.add.v2.f32 [%0], {%1,%2};"
                 :: "l"(addr), "f"(v.x), "f"(v.y) : "memory");
}

__device__ __forceinline__ void fma_row(float4& acc, float zv, float4 wv) {
    acc.x = fmaf(zv, wv.x, acc.x);
    acc.y = fmaf(zv, wv.y, acc.y);
    acc.z = fmaf(zv, wv.z, acc.z);
    acc.w = fmaf(zv, wv.w, acc.w);
}

// ---------------- noop (launch-order shim so ncu profiles edge_kernel) --------
__global__ void noop_kernel() {}

// ---------------- 0: zero scratch ----------------
__global__ void zero_kernel() {
    int idx = blockIdx.x * blockDim.x + threadIdx.x;
    int stride = gridDim.x * blockDim.x;
    const int n4 = (Nn * Hh) / 4;
    float4 z4 = make_float4(0.f, 0.f, 0.f, 0.f);
    for (int i = idx; i < n4; i += stride) {
        reinterpret_cast<float4*>(g_esum)[i] = z4;
        reinterpret_cast<float4*>(g_wsum)[i] = z4;
    }
    for (int i = idx; i < Bb * OUT; i += stride) g_pool[i] = 0.f;
    for (int i = idx; i < Bb; i += stride) g_cnt[i] = 0.f;
    for (int i = idx; i < 3 * 128; i += stride) g_stats[i] = 0.0;
}

// ---------------- 1: node encoder  h = x @ node_w + node_b  [N,64]->[N,32] ----
__global__ void __launch_bounds__(128) enc_kernel(const float* __restrict__ x,
                                                  const float* __restrict__ W,
                                                  const float* __restrict__ bias) {
    __shared__ __align__(16) float zs[64 * 68];
    __shared__ __align__(16) float ws[FIN * Hh];   // 64x32
    int tid = threadIdx.x;
    int n0 = blockIdx.x * 64;
    for (int i = tid; i < FIN * Hh; i += 128) ws[i] = W[i];
    for (int i = tid; i < 64 * FIN; i += 128) {
        int n = i >> 6, k = i & 63;
        int gn = n0 + n;
        zs[n * 68 + k] = (gn < Nn) ? x[(size_t)gn * FIN + k] : 0.f;
    }
    __syncthreads();
    int ti = tid >> 3, tj = tid & 7;           // 16 x 8
    float4 acc0 = {0,0,0,0}, acc1 = {0,0,0,0}, acc2 = {0,0,0,0}, acc3 = {0,0,0,0};
    const float4* ws4 = reinterpret_cast<const float4*>(ws); // [k][8]
    #pragma unroll
    for (int k4 = 0; k4 < 16; k4++) {
        float4 z0 = *reinterpret_cast<const float4*>(zs + (4*ti+0)*68 + 4*k4);
        float4 z1 = *reinterpret_cast<const float4*>(zs + (4*ti+1)*68 + 4*k4);
        float4 z2 = *reinterpret_cast<const float4*>(zs + (4*ti+2)*68 + 4*k4);
        float4 z3 = *reinterpret_cast<const float4*>(zs + (4*ti+3)*68 + 4*k4);
        float4 w0 = ws4[(4*k4+0)*8 + tj];
        float4 w1 = ws4[(4*k4+1)*8 + tj];
        float4 w2 = ws4[(4*k4+2)*8 + tj];
        float4 w3 = ws4[(4*k4+3)*8 + tj];
        fma_row(acc0, z0.x, w0); fma_row(acc0, z0.y, w1); fma_row(acc0, z0.z, w2); fma_row(acc0, z0.w, w3);
        fma_row(acc1, z1.x, w0); fma_row(acc1, z1.y, w1); fma_row(acc1, z1.z, w2); fma_row(acc1, z1.w, w3);
        fma_row(acc2, z2.x, w0); fma_row(acc2, z2.y, w1); fma_row(acc2, z2.z, w2); fma_row(acc2, z2.w, w3);
        fma_row(acc3, z3.x, w0); fma_row(acc3, z3.y, w1); fma_row(acc3, z3.z, w2); fma_row(acc3, z3.w, w3);
    }
    float4 bb = *reinterpret_cast<const float4*>(bias + 4*tj);
    float4 accs[4] = {acc0, acc1, acc2, acc3};
    #pragma unroll
    for (int r = 0; r < 4; r++) {
        int gn = n0 + 4*ti + r;
        if (gn < Nn) {
            float4 v = accs[r];
            v.x += bb.x; v.y += bb.y; v.z += bb.z; v.w += bb.w;
            *reinterpret_cast<float4*>(g_h + (size_t)gn * Hh + 4*tj) = v;
        }
    }
}

// ---------------- 2: edge pass — register-resident weights, 16 lanes/edge -----
// thread j2 = tid & 15 owns features (2*j2, 2*j2+1); el = tid >> 4 is edge 0..15
__global__ void __launch_bounds__(256, 3) edge_kernel(const int* __restrict__ ei,
                                                      const float* __restrict__ eattr,
                                                      const float* __restrict__ ew,
                                                      const float* __restrict__ eb) {
    __shared__ __align__(16) float sattr[16 * EIN];   // 16 edges x 16 attrs
    __shared__ int ssrc[16];
    __shared__ int sdst[16];
    int tid = threadIdx.x;
    int j2 = tid & 15;        // feature pair (2*j2, 2*j2+1)
    int el = tid >> 4;        // edge within tile (0..15)
    // register-resident weight column slice: W[k][2*j2 .. 2*j2+1], k = 0..15
    float2 wcol[EIN];
    #pragma unroll
    for (int k = 0; k < EIN; k++)
        wcol[k] = *reinterpret_cast<const float2*>(ew + k * Hh + 2 * j2);
    float2 eb2 = *reinterpret_cast<const float2*>(eb + 2 * j2);
    const int ntiles = Ee / 16;
    for (int t = blockIdx.x; t < ntiles; t += gridDim.x) {
        int e0 = t * 16;
        __syncthreads();
        {
            sattr[tid] = eattr[(size_t)e0 * EIN + tid];   // 256 floats, coalesced
            if (tid < 16) ssrc[tid] = ei[e0 + tid];
            else if (tid < 32) sdst[tid - 16] = ei[Ee + e0 + (tid - 16)];
        }
        __syncthreads();
        int src = ssrc[el], dst = sdst[el];
        float2 ea = eb2;
        const float4* a4p = reinterpret_cast<const float4*>(sattr + el * EIN);
        #pragma unroll
        for (int k4 = 0; k4 < 4; k4++) {
            float4 a4 = a4p[k4];       // broadcast across the 16 lanes of this edge
            float2 w0 = wcol[4*k4+0], w1 = wcol[4*k4+1];
            float2 w2 = wcol[4*k4+2], w3 = wcol[4*k4+3];
            ea.x = fmaf(a4.x, w0.x, ea.x); ea.y = fmaf(a4.x, w0.y, ea.y);
            ea.x = fmaf(a4.y, w1.x, ea.x); ea.y = fmaf(a4.y, w1.y, ea.y);
            ea.x = fmaf(a4.z, w2.x, ea.x); ea.y = fmaf(a4.z, w2.y, ea.y);
            ea.x = fmaf(a4.w, w3.x, ea.x); ea.y = fmaf(a4.w, w3.y, ea.y);
        }
        float2 hv = *reinterpret_cast<const float2*>(g_h + (size_t)src * Hh + 2 * j2);
        float2 m;
        m.x = fmaxf(hv.x + ea.x, 0.f) + EPS_GEN;
        m.y = fmaxf(hv.y + ea.y, 0.f) + EPS_GEN;
        float2 p;
        p.x = __expf(m.x); p.y = __expf(m.y);
        red_add_v2(g_esum + (size_t)dst * Hh + 2 * j2, p);
        red_add_v2(g_wsum + (size_t)dst * Hh + 2 * j2, make_float2(m.x * p.x, m.y * p.y));
    }
}

// ---------------- 3: stage A  out32 = agg + h ; y1 = out32@W1+b1 ; stats1 ------
__global__ void __launch_bounds__(256) stageA_kernel(const float* __restrict__ W,
                                                     const float* __restrict__ bias) {
    __shared__ __align__(16) float zs[64 * 36];
    __shared__ __align__(16) float ws[Hh * OUT];   // 32x64
    __shared__ float ssum[64], ssq[64];
    int tid = threadIdx.x;
    int n0 = blockIdx.x * 64;
    for (int i = tid; i < Hh * OUT; i += 256) ws[i] = W[i];
    if (tid < 64) { ssum[tid] = 0.f; ssq[tid] = 0.f; }
    for (int i = tid; i < 64 * Hh; i += 256) {
        int n = i >> 5, k = i & 31;
        int gn = n0 + n;
        float z = 0.f;
        if (gn < Nn) {
            float es = g_esum[(size_t)gn * Hh + k];
            float agg = (es > 0.f) ? g_wsum[(size_t)gn * Hh + k] / es : 0.f;
            z = agg + g_h[(size_t)gn * Hh + k];
        }
        zs[n * 36 + k] = z;
    }
    __syncthreads();
    int ti = tid >> 4, tj = tid & 15;
    float4 acc0 = {0,0,0,0}, acc1 = {0,0,0,0}, acc2 = {0,0,0,0}, acc3 = {0,0,0,0};
    const float4* ws4 = reinterpret_cast<const float4*>(ws); // [k][16]
    #pragma unroll
    for (int k4 = 0; k4 < 8; k4++) {
        float4 z0 = *reinterpret_cast<const float4*>(zs + (4*ti+0)*36 + 4*k4);
        float4 z1 = *reinterpret_cast<const float4*>(zs + (4*ti+1)*36 + 4*k4);
        float4 z2 = *reinterpret_cast<const float4*>(zs + (4*ti+2)*36 + 4*k4);
        float4 z3 = *reinterpret_cast<const float4*>(zs + (4*ti+3)*36 + 4*k4);
        float4 w0 = ws4[(4*k4+0)*16 + tj];
        float4 w1 = ws4[(4*k4+1)*16 + tj];
        float4 w2 = ws4[(4*k4+2)*16 + tj];
        float4 w3 = ws4[(4*k4+3)*16 + tj];
        fma_row(acc0, z0.x, w0); fma_row(acc0, z0.y, w1); fma_row(acc0, z0.z, w2); fma_row(acc0, z0.w, w3);
        fma_row(acc1, z1.x, w0); fma_row(acc1, z1.y, w1); fma_row(acc1, z1.z, w2); fma_row(acc1, z1.w, w3);
        fma_row(acc2, z2.x, w0); fma_row(acc2, z2.y, w1); fma_row(acc2, z2.z, w2); fma_row(acc2, z2.w, w3);
        fma_row(acc3, z3.x, w0); fma_row(acc3, z3.y, w1); fma_row(acc3, z3.z, w2); fma_row(acc3, z3.w, w3);
    }
    float4 bb = *reinterpret_cast<const float4*>(bias + 4*tj);
    float4 accs[4] = {acc0, acc1, acc2, acc3};
    float4 ls = {0,0,0,0}, lq = {0,0,0,0};
    #pragma unroll
    for (int r = 0; r < 4; r++) {
        int gn = n0 + 4*ti + r;
        if (gn < Nn) {
            float4 v = accs[r];
            v.x += bb.x; v.y += bb.y; v.z += bb.z; v.w += bb.w;
            *reinterpret_cast<float4*>(g_y1 + (size_t)gn * OUT + 4*tj) = v;
            ls.x += v.x; ls.y += v.y; ls.z += v.z; ls.w += v.w;
            lq.x += v.x*v.x; lq.y += v.y*v.y; lq.z += v.z*v.z; lq.w += v.w*v.w;
        }
    }
    atomicAdd(&ssum[4*tj+0], ls.x); atomicAdd(&ssum[4*tj+1], ls.y);
    atomicAdd(&ssum[4*tj+2], ls.z); atomicAdd(&ssum[4*tj+3], ls.w);
    atomicAdd(&ssq[4*tj+0], lq.x);  atomicAdd(&ssq[4*tj+1], lq.y);
    atomicAdd(&ssq[4*tj+2], lq.z);  atomicAdd(&ssq[4*tj+3], lq.w);
    __syncthreads();
    if (tid < 64) {
        atomicAdd(&g_stats[tid],      (double)ssum[tid]);
        atomicAdd(&g_stats[64 + tid], (double)ssq[tid]);
    }
}

// ---------------- 4: stages B/C  z=relu(bn(in)) ; out=z@W+b ; stats ------------
__global__ void __launch_bounds__(256) stageBC_kernel(const float* __restrict__ W,
                                                      const float* __restrict__ bias,
                                                      const float* __restrict__ gam,
                                                      const float* __restrict__ bet,
                                                      int sel) {
    __shared__ __align__(16) float zs[64 * 68];
    __shared__ __align__(16) float ws[OUT * OUT];  // 64x64
    __shared__ float ssum[64], ssq[64], sscale[64], sshift[64];
    const float* in  = sel ? g_y2 : g_y1;
    float*       out = sel ? g_y3 : g_y2;
    int sin  = sel ? 128 : 0;
    int sout = sel ? 256 : 128;
    int tid = threadIdx.x;
    int n0 = blockIdx.x * 64;
    for (int i = tid; i < OUT * OUT; i += 256) ws[i] = W[i];
    if (tid < 64) {
        double mean = g_stats[sin + tid] / (double)Nn;
        double msq  = g_stats[sin + 64 + tid] / (double)Nn;
        double var  = msq - mean * mean;
        float sc = gam[tid] * rsqrtf((float)var + EPS_BN);
        sscale[tid] = sc;
        sshift[tid] = bet[tid] - (float)mean * sc;
        ssum[tid] = 0.f; ssq[tid] = 0.f;
    }
    __syncthreads();
    for (int i = tid; i < 64 * OUT; i += 256) {
        int n = i >> 6, k = i & 63;
        int gn = n0 + n;
        float z = 0.f;
        if (gn < Nn) z = fmaxf(sscale[k] * in[(size_t)gn * OUT + k] + sshift[k], 0.f);
        zs[n * 68 + k] = z;
    }
    __syncthreads();
    int ti = tid >> 4, tj = tid & 15;
    float4 acc0 = {0,0,0,0}, acc1 = {0,0,0,0}, acc2 = {0,0,0,0}, acc3 = {0,0,0,0};
    const float4* ws4 = reinterpret_cast<const float4*>(ws);
    #pragma unroll
    for (int k4 = 0; k4 < 16; k4++) {
        float4 z0 = *reinterpret_cast<const float4*>(zs + (4*ti+0)*68 + 4*k4);
        float4 z1 = *reinterpret_cast<const float4*>(zs + (4*ti+1)*68 + 4*k4);
        float4 z2 = *reinterpret_cast<const float4*>(zs + (4*ti+2)*68 + 4*k4);
        float4 z3 = *reinterpret_cast<const float4*>(zs + (4*ti+3)*68 + 4*k4);
        float4 w0 = ws4[(4*k4+0)*16 + tj];
        float4 w1 = ws4[(4*k4+1)*16 + tj];
        float4 w2 = ws4[(4*k4+2)*16 + tj];
        float4 w3 = ws4[(4*k4+3)*16 + tj];
        fma_row(acc0, z0.x, w0); fma_row(acc0, z0.y, w1); fma_row(acc0, z0.z, w2); fma_row(acc0, z0.w, w3);
        fma_row(acc1, z1.x, w0); fma_row(acc1, z1.y, w1); fma_row(acc1, z1.z, w2); fma_row(acc1, z1.w, w3);
        fma_row(acc2, z2.x, w0); fma_row(acc2, z2.y, w1); fma_row(acc2, z2.z, w2); fma_row(acc2, z2.w, w3);
        fma_row(acc3, z3.x, w0); fma_row(acc3, z3.y, w1); fma_row(acc3, z3.z, w2); fma_row(acc3, z3.w, w3);
    }
    float4 bb = *reinterpret_cast<const float4*>(bias + 4*tj);
    float4 accs[4] = {acc0, acc1, acc2, acc3};
    float4 ls = {0,0,0,0}, lq = {0,0,0,0};
    #pragma unroll
    for (int r = 0; r < 4; r++) {
        int gn = n0 + 4*ti + r;
        if (gn < Nn) {
            float4 v = accs[r];
            v.x += bb.x; v.y += bb.y; v.z += bb.z; v.w += bb.w;
            *reinterpret_cast<float4*>(out + (size_t)gn * OUT + 4*tj) = v;
            ls.x += v.x; ls.y += v.y; ls.z += v.z; ls.w += v.w;
            lq.x += v.x*v.x; lq.y += v.y*v.y; lq.z += v.z*v.z; lq.w += v.w*v.w;
        }
    }
    atomicAdd(&ssum[4*tj+0], ls.x); atomicAdd(&ssum[4*tj+1], ls.y);
    atomicAdd(&ssum[4*tj+2], ls.z); atomicAdd(&ssum[4*tj+3], ls.w);
    atomicAdd(&ssq[4*tj+0], lq.x);  atomicAdd(&ssq[4*tj+1], lq.y);
    atomicAdd(&ssq[4*tj+2], lq.z);  atomicAdd(&ssq[4*tj+3], lq.w);
    __syncthreads();
    if (tid < 64) {
        atomicAdd(&g_stats[sout + tid],      (double)ssum[tid]);
        atomicAdd(&g_stats[sout + 64 + tid], (double)ssq[tid]);
    }
}

// ---------------- 5: stage D  node_out = relu(bn3(y3))@W4+b4, pooled -----------
__global__ void __launch_bounds__(256) stageD_kernel(const float* __restrict__ W,
                                                     const float* __restrict__ bias,
                                                     const float* __restrict__ gam,
                                                     const float* __restrict__ bet,
                                                     const int* __restrict__ batch) {
    __shared__ __align__(16) float zs[64 * 68];
    __shared__ __align__(16) float ws[OUT * OUT];
    __shared__ float sscale[64], sshift[64];
    int tid = threadIdx.x;
    int n0 = blockIdx.x * 64;
    for (int i = tid; i < OUT * OUT; i += 256) ws[i] = W[i];
    if (tid < 64) {
        double mean = g_stats[256 + tid] / (double)Nn;
        double msq  = g_stats[256 + 64 + tid] / (double)Nn;
        double var  = msq - mean * mean;
        float sc = gam[tid] * rsqrtf((float)var + EPS_BN);
        sscale[tid] = sc;
        sshift[tid] = bet[tid] - (float)mean * sc;
    }
    __syncthreads();
    for (int i = tid; i < 64 * OUT; i += 256) {
        int n = i >> 6, k = i & 63;
        int gn = n0 + n;
        float z = 0.f;
        if (gn < Nn) z = fmaxf(sscale[k] * g_y3[(size_t)gn * OUT + k] + sshift[k], 0.f);
        zs[n * 68 + k] = z;
    }
    __syncthreads();
    int ti = tid >> 4, tj = tid & 15;
    float4 acc0 = {0,0,0,0}, acc1 = {0,0,0,0}, acc2 = {0,0,0,0}, acc3 = {0,0,0,0};
    const float4* ws4 = reinterpret_cast<const float4*>(ws);
    #pragma unroll
    for (int k4 = 0; k4 < 16; k4++) {
        float4 z0 = *reinterpret_cast<const float4*>(zs + (4*ti+0)*68 + 4*k4);
        float4 z1 = *reinterpret_cast<const float4*>(zs + (4*ti+1)*68 + 4*k4);
        float4 z2 = *reinterpret_cast<const float4*>(zs + (4*ti+2)*68 + 4*k4);
        float4 z3 = *reinterpret_cast<const float4*>(zs + (4*ti+3)*68 + 4*k4);
        float4 w0 = ws4[(4*k4+0)*16 + tj];
        float4 w1 = ws4[(4*k4+1)*16 + tj];
        float4 w2 = ws4[(4*k4+2)*16 + tj];
        float4 w3 = ws4[(4*k4+3)*16 + tj];
        fma_row(acc0, z0.x, w0); fma_row(acc0, z0.y, w1); fma_row(acc0, z0.z, w2); fma_row(acc0, z0.w, w3);
        fma_row(acc1, z1.x, w0); fma_row(acc1, z1.y, w1); fma_row(acc1, z1.z, w2); fma_row(acc1, z1.w, w3);
        fma_row(acc2, z2.x, w0); fma_row(acc2, z2.y, w1); fma_row(acc2, z2.z, w2); fma_row(acc2, z2.w, w3);
        fma_row(acc3, z3.x, w0); fma_row(acc3, z3.y, w1); fma_row(acc3, z3.z, w2); fma_row(acc3, z3.w, w3);
    }
    float4 bb = *reinterpret_cast<const float4*>(bias + 4*tj);
    float4 accs[4] = {acc0, acc1, acc2, acc3};
    #pragma unroll
    for (int r = 0; r < 4; r++) {
        int gn = n0 + 4*ti + r;
        if (gn < Nn) {
            float4 v = accs[r];
            v.x += bb.x; v.y += bb.y; v.z += bb.z; v.w += bb.w;
            int g = batch[gn];
            red_add_v4(&g_pool[(size_t)g * OUT + 4*tj], v);
            if (tj == 0) atomicAdd(&g_cnt[g], 1.0f);
        }
    }
}

// ---------------- 6: head (per graph) -----------------------------------------
__global__ void head_kernel(const float* __restrict__ action,
                            const float* __restrict__ pinw, const float* __restrict__ pinb,
                            const float* __restrict__ phw,  const float* __restrict__ phb,
                            const float* __restrict__ pow_, const float* __restrict__ pob,
                            float* __restrict__ outp) {
    int g = threadIdx.x;
    if (g >= Bb) return;
    float inv = 1.0f / fmaxf(g_cnt[g], 1.0f);
    float fp[16];
    #pragma unroll
    for (int jj = 0; jj < 16; jj++) {
        float s = 0.f;
        for (int f = 0; f < OUT; f++) s += g_pool[g * OUT + f] * pinw[f * 16 + jj];
        fp[jj] = fmaxf(s * inv + pinb[jj], 0.f);
    }
    float res = pob[0];
    #pragma unroll
    for (int q = 0; q < 10; q++) {
        float s = phb[q];
        #pragma unroll
        for (int jj = 0; jj < 16; jj++) s += fp[jj] * phw[jj * 10 + q];
        #pragma unroll
        for (int a = 0; a < ADIM; a++) s += action[g * ADIM + a] * phw[(16 + a) * 10 + q];
        res += fmaxf(s, 0.f) * pow_[q];
    }
    outp[g] = res;
}

// ---------------- launch -------------------------------------------------------
extern "C" void kernel_launch(void* const* d_in, const int* in_sizes, int n_in,
                              void* d_out, int out_size) {
    const float* x      = (const float*)d_in[0];
    const int*   ei     = (const int*)  d_in[1];
    const float* eattr  = (const float*)d_in[2];
    const int*   batch  = (const int*)  d_in[3];
    const float* action = (const float*)d_in[4];
    const float* node_w = (const float*)d_in[5];
    const float* node_b = (const float*)d_in[6];
    const float* edge_w = (const float*)d_in[7];
    const float* edge_b = (const float*)d_in[8];
    const float* w1 = (const float*)d_in[9];  const float* b1 = (const float*)d_in[10];
    const float* g1 = (const float*)d_in[11]; const float* bb1 = (const float*)d_in[12];
    const float* w2 = (const float*)d_in[13]; const float* b2 = (const float*)d_in[14];
    const float* g2 = (const float*)d_in[15]; const float* bb2 = (const float*)d_in[16];
    const float* w3 = (const float*)d_in[17]; const float* b3 = (const float*)d_in[18];
    const float* g3 = (const float*)d_in[19]; const float* bb3 = (const float*)d_in[20];
    const float* w4 = (const float*)d_in[21]; const float* b4 = (const float*)d_in[22];
    const float* pinw = (const float*)d_in[23]; const float* pinb = (const float*)d_in[24];
    const float* phw  = (const float*)d_in[25]; const float* phb  = (const float*)d_in[26];
    const float* pow_ = (const float*)d_in[27]; const float* pob  = (const float*)d_in[28];

    const int NBLK = (Nn + 63) / 64;  // 1563

    zero_kernel<<<2048, 256>>>();                       // 1
    enc_kernel<<<NBLK, 128>>>(x, node_w, node_b);       // 2
    noop_kernel<<<1, 32>>>();                           // 3
    edge_kernel<<<2048, 256>>>(ei, eattr, edge_w, edge_b); // 4 <- ncu captures this
    stageA_kernel<<<NBLK, 256>>>(w1, b1);
    stageBC_kernel<<<NBLK, 256>>>(w2, b2, g1, bb1, 0);
    stageBC_kernel<<<NBLK, 256>>>(w3, b3, g2, bb2, 1);
    stageD_kernel<<<NBLK, 256>>>(w4, b4, g3, bb3, batch);
    head_kernel<<<1, 64>>>(action, pinw, pinb, phw, phb, pow_, pob, (float*)d_out);
}

// round 16
// speedup vs baseline: 1.5958x; 1.5958x over previous
#include <cuda_runtime.h>
#include <cuda_bf16.h>
#include <cstdint>

#define Nn 100000
#define Ee 3200000
#define Bb 64
#define FIN 64
#define EIN 16
#define ADIM 13
#define Hh 32
#define OUT 64
#define EPS_GEN 1e-7f
#define EPS_BN 1e-5f

// ---------------- scratch (device globals; no allocs allowed) ----------------
__device__ float  g_h[Nn * Hh];        // node encoder output [N,32]
__device__ float  g_esum[Nn * Hh];     // sum of exp(msg) per dst
__device__ float  g_wsum[Nn * Hh];     // sum of msg*exp(msg) per dst
__device__ float  g_y1[Nn * OUT];
__device__ float  g_y2[Nn * OUT];
__device__ float  g_y3[Nn * OUT];
__device__ double g_stats[3 * 128];    // per stage: [sum(64) | sumsq(64)]
__device__ float  g_pool[Bb * OUT];
__device__ float  g_cnt[Bb];

// ---------------- helpers ----------------
__device__ __forceinline__ void red_add_v4(float* addr, float4 v) {
    asm volatile("red.global.add.v4.f32 [%0], {%1,%2,%3,%4};"
                 :: "l"(addr), "f"(v.x), "f"(v.y), "f"(v.z), "f"(v.w) : "memory");
}

__device__ __forceinline__ void fma_row(float4& acc, float zv, float4 wv) {
    acc.x = fmaf(zv, wv.x, acc.x);
    acc.y = fmaf(zv, wv.y, acc.y);
    acc.z = fmaf(zv, wv.z, acc.z);
    acc.w = fmaf(zv, wv.w, acc.w);
}

// ---------------- noop (launch-order shim so ncu profiles edge_kernel) --------
__global__ void noop_kernel() {}

// ---------------- 0: zero scratch ----------------
__global__ void zero_kernel() {
    int idx = blockIdx.x * blockDim.x + threadIdx.x;
    int stride = gridDim.x * blockDim.x;
    const int n4 = (Nn * Hh) / 4;
    float4 z4 = make_float4(0.f, 0.f, 0.f, 0.f);
    for (int i = idx; i < n4; i += stride) {
        reinterpret_cast<float4*>(g_esum)[i] = z4;
        reinterpret_cast<float4*>(g_wsum)[i] = z4;
    }
    for (int i = idx; i < Bb * OUT; i += stride) g_pool[i] = 0.f;
    for (int i = idx; i < Bb; i += stride) g_cnt[i] = 0.f;
    for (int i = idx; i < 3 * 128; i += stride) g_stats[i] = 0.0;
}

// ---------------- 1: node encoder  h = x @ node_w + node_b  [N,64]->[N,32] ----
__global__ void __launch_bounds__(128) enc_kernel(const float* __restrict__ x,
                                                  const float* __restrict__ W,
                                                  const float* __restrict__ bias) {
    __shared__ __align__(16) float zs[64 * 68];
    __shared__ __align__(16) float ws[FIN * Hh];   // 64x32
    int tid = threadIdx.x;
    int n0 = blockIdx.x * 64;
    for (int i = tid; i < FIN * Hh; i += 128) ws[i] = W[i];
    for (int i = tid; i < 64 * FIN; i += 128) {
        int n = i >> 6, k = i & 63;
        int gn = n0 + n;
        zs[n * 68 + k] = (gn < Nn) ? x[(size_t)gn * FIN + k] : 0.f;
    }
    __syncthreads();
    int ti = tid >> 3, tj = tid & 7;           // 16 x 8
    float4 acc0 = {0,0,0,0}, acc1 = {0,0,0,0}, acc2 = {0,0,0,0}, acc3 = {0,0,0,0};
    const float4* ws4 = reinterpret_cast<const float4*>(ws); // [k][8]
    #pragma unroll
    for (int k4 = 0; k4 < 16; k4++) {
        float4 z0 = *reinterpret_cast<const float4*>(zs + (4*ti+0)*68 + 4*k4);
        float4 z1 = *reinterpret_cast<const float4*>(zs + (4*ti+1)*68 + 4*k4);
        float4 z2 = *reinterpret_cast<const float4*>(zs + (4*ti+2)*68 + 4*k4);
        float4 z3 = *reinterpret_cast<const float4*>(zs + (4*ti+3)*68 + 4*k4);
        float4 w0 = ws4[(4*k4+0)*8 + tj];
        float4 w1 = ws4[(4*k4+1)*8 + tj];
        float4 w2 = ws4[(4*k4+2)*8 + tj];
        float4 w3 = ws4[(4*k4+3)*8 + tj];
        fma_row(acc0, z0.x, w0); fma_row(acc0, z0.y, w1); fma_row(acc0, z0.z, w2); fma_row(acc0, z0.w, w3);
        fma_row(acc1, z1.x, w0); fma_row(acc1, z1.y, w1); fma_row(acc1, z1.z, w2); fma_row(acc1, z1.w, w3);
        fma_row(acc2, z2.x, w0); fma_row(acc2, z2.y, w1); fma_row(acc2, z2.z, w2); fma_row(acc2, z2.w, w3);
        fma_row(acc3, z3.x, w0); fma_row(acc3, z3.y, w1); fma_row(acc3, z3.z, w2); fma_row(acc3, z3.w, w3);
    }
    float4 bb = *reinterpret_cast<const float4*>(bias + 4*tj);
    float4 accs[4] = {acc0, acc1, acc2, acc3};
    #pragma unroll
    for (int r = 0; r < 4; r++) {
        int gn = n0 + 4*ti + r;
        if (gn < Nn) {
            float4 v = accs[r];
            v.x += bb.x; v.y += bb.y; v.z += bb.z; v.w += bb.w;
            *reinterpret_cast<float4*>(g_h + (size_t)gn * Hh + 4*tj) = v;
        }
    }
}

// ---------------- 2: edge pass (32 edges/tile, register double-buffered) ------
__global__ void __launch_bounds__(256) edge_kernel(const int* __restrict__ ei,
                                                   const float* __restrict__ eattr,
                                                   const float* __restrict__ ew,
                                                   const float* __restrict__ eb) {
    __shared__ __align__(16) float sattr[32 * 20];
    __shared__ __align__(16) float sws[EIN * Hh];   // 16x32
    __shared__ int ssrc[32];
    __shared__ int sdst[32];
    int tid = threadIdx.x;
    for (int i = tid; i < EIN * Hh; i += 256) sws[i] = ew[i];
    int j = tid & 7;          // feature quad (feats 4j..4j+3)
    int el = tid >> 3;        // edge within tile (0..31)
    float4 eb4 = *reinterpret_cast<const float4*>(eb + 4*j);
    const float4* w4p = reinterpret_cast<const float4*>(sws); // [k][8]
    const int ntiles = Ee / 32;

    // prefetch first tile into registers
    int t = blockIdx.x;
    float2 vn = make_float2(0.f, 0.f);
    int xn = 0;
    if (t < ntiles) {
        vn = reinterpret_cast<const float2*>(eattr + (size_t)t * 32 * EIN)[tid];
        if (tid < 32) xn = ei[t * 32 + tid];
        else if (tid < 64) xn = ei[Ee + t * 32 + (tid - 32)];
    }

    for (; t < ntiles; t += gridDim.x) {
        float2 vc = vn;
        int xc = xn;
        __syncthreads();   // previous tile's compute done reading smem
        {
            int row = tid >> 3, col = (tid & 7) * 2;
            sattr[row * 20 + col]     = vc.x;
            sattr[row * 20 + col + 1] = vc.y;
            if (tid < 32) ssrc[tid] = xc;
            else if (tid < 64) sdst[tid - 32] = xc;
        }
        __syncthreads();
        // issue next tile's loads now; they complete while we compute
        int tn = t + gridDim.x;
        if (tn < ntiles) {
            vn = reinterpret_cast<const float2*>(eattr + (size_t)tn * 32 * EIN)[tid];
            if (tid < 32) xn = ei[tn * 32 + tid];
            else if (tid < 64) xn = ei[Ee + tn * 32 + (tid - 32)];
        }
        int src = ssrc[el], dst = sdst[el];
        float4 ea = eb4;
        const float4* a4p = reinterpret_cast<const float4*>(sattr + el * 20);
        #pragma unroll
        for (int k4 = 0; k4 < 4; k4++) {
            float4 a4 = a4p[k4];
            float4 w0 = w4p[(4*k4+0)*8 + j];
            float4 w1 = w4p[(4*k4+1)*8 + j];
            float4 w2 = w4p[(4*k4+2)*8 + j];
            float4 w3 = w4p[(4*k4+3)*8 + j];
            fma_row(ea, a4.x, w0); fma_row(ea, a4.y, w1); fma_row(ea, a4.z, w2); fma_row(ea, a4.w, w3);
        }
        float4 hv = *reinterpret_cast<const float4*>(g_h + (size_t)src * Hh + 4*j);
        float4 m;
        m.x = fmaxf(hv.x + ea.x, 0.f) + EPS_GEN;
        m.y = fmaxf(hv.y + ea.y, 0.f) + EPS_GEN;
        m.z = fmaxf(hv.z + ea.z, 0.f) + EPS_GEN;
        m.w = fmaxf(hv.w + ea.w, 0.f) + EPS_GEN;
        float4 p;
        p.x = __expf(m.x); p.y = __expf(m.y); p.z = __expf(m.z); p.w = __expf(m.w);
        red_add_v4(g_esum + (size_t)dst * Hh + 4*j, p);
        red_add_v4(g_wsum + (size_t)dst * Hh + 4*j,
                   make_float4(m.x*p.x, m.y*p.y, m.z*p.z, m.w*p.w));
    }
}

// ---------------- 3: stage A  out32 = agg + h ; y1 = out32@W1+b1 ; stats1 ------
__global__ void __launch_bounds__(256) stageA_kernel(const float* __restrict__ W,
                                                     const float* __restrict__ bias) {
    __shared__ __align__(16) float zs[64 * 36];
    __shared__ __align__(16) float ws[Hh * OUT];   // 32x64
    __shared__ float ssum[64], ssq[64];
    int tid = threadIdx.x;
    int n0 = blockIdx.x * 64;
    for (int i = tid; i < Hh * OUT; i += 256) ws[i] = W[i];
    if (tid < 64) { ssum[tid] = 0.f; ssq[tid] = 0.f; }
    for (int i = tid; i < 64 * Hh; i += 256) {
        int n = i >> 5, k = i & 31;
        int gn = n0 + n;
        float z = 0.f;
        if (gn < Nn) {
            float es = g_esum[(size_t)gn * Hh + k];
            float agg = (es > 0.f) ? g_wsum[(size_t)gn * Hh + k] / es : 0.f;
            z = agg + g_h[(size_t)gn * Hh + k];
        }
        zs[n * 36 + k] = z;
    }
    __syncthreads();
    int ti = tid >> 4, tj = tid & 15;
    float4 acc0 = {0,0,0,0}, acc1 = {0,0,0,0}, acc2 = {0,0,0,0}, acc3 = {0,0,0,0};
    const float4* ws4 = reinterpret_cast<const float4*>(ws); // [k][16]
    #pragma unroll
    for (int k4 = 0; k4 < 8; k4++) {
        float4 z0 = *reinterpret_cast<const float4*>(zs + (4*ti+0)*36 + 4*k4);
        float4 z1 = *reinterpret_cast<const float4*>(zs + (4*ti+1)*36 + 4*k4);
        float4 z2 = *reinterpret_cast<const float4*>(zs + (4*ti+2)*36 + 4*k4);
        float4 z3 = *reinterpret_cast<const float4*>(zs + (4*ti+3)*36 + 4*k4);
        float4 w0 = ws4[(4*k4+0)*16 + tj];
        float4 w1 = ws4[(4*k4+1)*16 + tj];
        float4 w2 = ws4[(4*k4+2)*16 + tj];
        float4 w3 = ws4[(4*k4+3)*16 + tj];
        fma_row(acc0, z0.x, w0); fma_row(acc0, z0.y, w1); fma_row(acc0, z0.z, w2); fma_row(acc0, z0.w, w3);
        fma_row(acc1, z1.x, w0); fma_row(acc1, z1.y, w1); fma_row(acc1, z1.z, w2); fma_row(acc1, z1.w, w3);
        fma_row(acc2, z2.x, w0); fma_row(acc2, z2.y, w1); fma_row(acc2, z2.z, w2); fma_row(acc2, z2.w, w3);
        fma_row(acc3, z3.x, w0); fma_row(acc3, z3.y, w1); fma_row(acc3, z3.z, w2); fma_row(acc3, z3.w, w3);
    }
    float4 bb = *reinterpret_cast<const float4*>(bias + 4*tj);
    float4 accs[4] = {acc0, acc1, acc2, acc3};
    float4 ls = {0,0,0,0}, lq = {0,0,0,0};
    #pragma unroll
    for (int r = 0; r < 4; r++) {
        int gn = n0 + 4*ti + r;
        if (gn < Nn) {
            float4 v = accs[r];
            v.x += bb.x; v.y += bb.y; v.z += bb.z; v.w += bb.w;
            *reinterpret_cast<float4*>(g_y1 + (size_t)gn * OUT + 4*tj) = v;
            ls.x += v.x; ls.y += v.y; ls.z += v.z; ls.w += v.w;
            lq.x += v.x*v.x; lq.y += v.y*v.y; lq.z += v.z*v.z; lq.w += v.w*v.w;
        }
    }
    atomicAdd(&ssum[4*tj+0], ls.x); atomicAdd(&ssum[4*tj+1], ls.y);
    atomicAdd(&ssum[4*tj+2], ls.z); atomicAdd(&ssum[4*tj+3], ls.w);
    atomicAdd(&ssq[4*tj+0], lq.x);  atomicAdd(&ssq[4*tj+1], lq.y);
    atomicAdd(&ssq[4*tj+2], lq.z);  atomicAdd(&ssq[4*tj+3], lq.w);
    __syncthreads();
    if (tid < 64) {
        atomicAdd(&g_stats[tid],      (double)ssum[tid]);
        atomicAdd(&g_stats[64 + tid], (double)ssq[tid]);
    }
}

// ---------------- 4: stages B/C  z=relu(bn(in)) ; out=z@W+b ; stats ------------
__global__ void __launch_bounds__(256) stageBC_kernel(const float* __restrict__ W,
                                                      const float* __restrict__ bias,
                                                      const float* __restrict__ gam,
                                                      const float* __restrict__ bet,
                                                      int sel) {
    __shared__ __align__(16) float zs[64 * 68];
    __shared__ __align__(16) float ws[OUT * OUT];  // 64x64
    __shared__ float ssum[64], ssq[64], sscale[64], sshift[64];
    const float* in  = sel ? g_y2 : g_y1;
    float*       out = sel ? g_y3 : g_y2;
    int sin  = sel ? 128 : 0;
    int sout = sel ? 256 : 128;
    int tid = threadIdx.x;
    int n0 = blockIdx.x * 64;
    for (int i = tid; i < OUT * OUT; i += 256) ws[i] = W[i];
    if (tid < 64) {
        double mean = g_stats[sin + tid] / (double)Nn;
        double msq  = g_stats[sin + 64 + tid] / (double)Nn;
        double var  = msq - mean * mean;
        float sc = gam[tid] * rsqrtf((float)var + EPS_BN);
        sscale[tid] = sc;
        sshift[tid] = bet[tid] - (float)mean * sc;
        ssum[tid] = 0.f; ssq[tid] = 0.f;
    }
    __syncthreads();
    for (int i = tid; i < 64 * OUT; i += 256) {
        int n = i >> 6, k = i & 63;
        int gn = n0 + n;
        float z = 0.f;
        if (gn < Nn) z = fmaxf(sscale[k] * in[(size_t)gn * OUT + k] + sshift[k], 0.f);
        zs[n * 68 + k] = z;
    }
    __syncthreads();
    int ti = tid >> 4, tj = tid & 15;
    float4 acc0 = {0,0,0,0}, acc1 = {0,0,0,0}, acc2 = {0,0,0,0}, acc3 = {0,0,0,0};
    const float4* ws4 = reinterpret_cast<const float4*>(ws);
    #pragma unroll
    for (int k4 = 0; k4 < 16; k4++) {
        float4 z0 = *reinterpret_cast<const float4*>(zs + (4*ti+0)*68 + 4*k4);
        float4 z1 = *reinterpret_cast<const float4*>(zs + (4*ti+1)*68 + 4*k4);
        float4 z2 = *reinterpret_cast<const float4*>(zs + (4*ti+2)*68 + 4*k4);
        float4 z3 = *reinterpret_cast<const float4*>(zs + (4*ti+3)*68 + 4*k4);
        float4 w0 = ws4[(4*k4+0)*16 + tj];
        float4 w1 = ws4[(4*k4+1)*16 + tj];
        float4 w2 = ws4[(4*k4+2)*16 + tj];
        float4 w3 = ws4[(4*k4+3)*16 + tj];
        fma_row(acc0, z0.x, w0); fma_row(acc0, z0.y, w1); fma_row(acc0, z0.z, w2); fma_row(acc0, z0.w, w3);
        fma_row(acc1, z1.x, w0); fma_row(acc1, z1.y, w1); fma_row(acc1, z1.z, w2); fma_row(acc1, z1.w, w3);
        fma_row(acc2, z2.x, w0); fma_row(acc2, z2.y, w1); fma_row(acc2, z2.z, w2); fma_row(acc2, z2.w, w3);
        fma_row(acc3, z3.x, w0); fma_row(acc3, z3.y, w1); fma_row(acc3, z3.z, w2); fma_row(acc3, z3.w, w3);
    }
    float4 bb = *reinterpret_cast<const float4*>(bias + 4*tj);
    float4 accs[4] = {acc0, acc1, acc2, acc3};
    float4 ls = {0,0,0,0}, lq = {0,0,0,0};
    #pragma unroll
    for (int r = 0; r < 4; r++) {
        int gn = n0 + 4*ti + r;
        if (gn < Nn) {
            float4 v = accs[r];
            v.x += bb.x; v.y += bb.y; v.z += bb.z; v.w += bb.w;
            *reinterpret_cast<float4*>(out + (size_t)gn * OUT + 4*tj) = v;
            ls.x += v.x; ls.y += v.y; ls.z += v.z; ls.w += v.w;
            lq.x += v.x*v.x; lq.y += v.y*v.y; lq.z += v.z*v.z; lq.w += v.w*v.w;
        }
    }
    atomicAdd(&ssum[4*tj+0], ls.x); atomicAdd(&ssum[4*tj+1], ls.y);
    atomicAdd(&ssum[4*tj+2], ls.z); atomicAdd(&ssum[4*tj+3], ls.w);
    atomicAdd(&ssq[4*tj+0], lq.x);  atomicAdd(&ssq[4*tj+1], lq.y);
    atomicAdd(&ssq[4*tj+2], lq.z);  atomicAdd(&ssq[4*tj+3], lq.w);
    __syncthreads();
    if (tid < 64) {
        atomicAdd(&g_stats[sout + tid],      (double)ssum[tid]);
        atomicAdd(&g_stats[sout + 64 + tid], (double)ssq[tid]);
    }
}

// ---------------- 5: stage D  node_out = relu(bn3(y3))@W4+b4, pooled -----------
__global__ void __launch_bounds__(256) stageD_kernel(const float* __restrict__ W,
                                                     const float* __restrict__ bias,
                                                     const float* __restrict__ gam,
                                                     const float* __restrict__ bet,
                                                     const int* __restrict__ batch) {
    __shared__ __align__(16) float zs[64 * 68];
    __shared__ __align__(16) float ws[OUT * OUT];
    __shared__ float sscale[64], sshift[64];
    int tid = threadIdx.x;
    int n0 = blockIdx.x * 64;
    for (int i = tid; i < OUT * OUT; i += 256) ws[i] = W[i];
    if (tid < 64) {
        double mean = g_stats[256 + tid] / (double)Nn;
        double msq  = g_stats[256 + 64 + tid] / (double)Nn;
        double var  = msq - mean * mean;
        float sc = gam[tid] * rsqrtf((float)var + EPS_BN);
        sscale[tid] = sc;
        sshift[tid] = bet[tid] - (float)mean * sc;
    }
    __syncthreads();
    for (int i = tid; i < 64 * OUT; i += 256) {
        int n = i >> 6, k = i & 63;
        int gn = n0 + n;
        float z = 0.f;
        if (gn < Nn) z = fmaxf(sscale[k] * g_y3[(size_t)gn * OUT + k] + sshift[k], 0.f);
        zs[n * 68 + k] = z;
    }
    __syncthreads();
    int ti = tid >> 4, tj = tid & 15;
    float4 acc0 = {0,0,0,0}, acc1 = {0,0,0,0}, acc2 = {0,0,0,0}, acc3 = {0,0,0,0};
    const float4* ws4 = reinterpret_cast<const float4*>(ws);
    #pragma unroll
    for (int k4 = 0; k4 < 16; k4++) {
        float4 z0 = *reinterpret_cast<const float4*>(zs + (4*ti+0)*68 + 4*k4);
        float4 z1 = *reinterpret_cast<const float4*>(zs + (4*ti+1)*68 + 4*k4);
        float4 z2 = *reinterpret_cast<const float4*>(zs + (4*ti+2)*68 + 4*k4);
        float4 z3 = *reinterpret_cast<const float4*>(zs + (4*ti+3)*68 + 4*k4);
        float4 w0 = ws4[(4*k4+0)*16 + tj];
        float4 w1 = ws4[(4*k4+1)*16 + tj];
        float4 w2 = ws4[(4*k4+2)*16 + tj];
        float4 w3 = ws4[(4*k4+3)*16 + tj];
        fma_row(acc0, z0.x, w0); fma_row(acc0, z0.y, w1); fma_row(acc0, z0.z, w2); fma_row(acc0, z0.w, w3);
        fma_row(acc1, z1.x, w0); fma_row(acc1, z1.y, w1); fma_row(acc1, z1.z, w2); fma_row(acc1, z1.w, w3);
        fma_row(acc2, z2.x, w0); fma_row(acc2, z2.y, w1); fma_row(acc2, z2.z, w2); fma_row(acc2, z2.w, w3);
        fma_row(acc3, z3.x, w0); fma_row(acc3, z3.y, w1); fma_row(acc3, z3.z, w2); fma_row(acc3, z3.w, w3);
    }
    float4 bb = *reinterpret_cast<const float4*>(bias + 4*tj);
    float4 accs[4] = {acc0, acc1, acc2, acc3};
    #pragma unroll
    for (int r = 0; r < 4; r++) {
        int gn = n0 + 4*ti + r;
        if (gn < Nn) {
            float4 v = accs[r];
            v.x += bb.x; v.y += bb.y; v.z += bb.z; v.w += bb.w;
            int g = batch[gn];
            red_add_v4(&g_pool[(size_t)g * OUT + 4*tj], v);
            if (tj == 0) atomicAdd(&g_cnt[g], 1.0f);
        }
    }
}

// ---------------- 6: head (per graph) -----------------------------------------
__global__ void head_kernel(const float* __restrict__ action,
                            const float* __restrict__ pinw, const float* __restrict__ pinb,
                            const float* __restrict__ phw,  const float* __restrict__ phb,
                            const float* __restrict__ pow_, const float* __restrict__ pob,
                            float* __restrict__ outp) {
    int g = threadIdx.x;
    if (g >= Bb) return;
    float inv = 1.0f / fmaxf(g_cnt[g], 1.0f);
    float fp[16];
    #pragma unroll
    for (int jj = 0; jj < 16; jj++) {
        float s = 0.f;
        for (int f = 0; f < OUT; f++) s += g_pool[g * OUT + f] * pinw[f * 16 + jj];
        fp[jj] = fmaxf(s * inv + pinb[jj], 0.f);
    }
    float res = pob[0];
    #pragma unroll
    for (int q = 0; q < 10; q++) {
        float s = phb[q];
        #pragma unroll
        for (int jj = 0; jj < 16; jj++) s += fp[jj] * phw[jj * 10 + q];
        #pragma unroll
        for (int a = 0; a < ADIM; a++) s += action[g * ADIM + a] * phw[(16 + a) * 10 + q];
        res += fmaxf(s, 0.f) * pow_[q];
    }
    outp[g] = res;
}

// ---------------- launch -------------------------------------------------------
extern "C" void kernel_launch(void* const* d_in, const int* in_sizes, int n_in,
                              void* d_out, int out_size) {
    const float* x      = (const float*)d_in[0];
    const int*   ei     = (const int*)  d_in[1];
    const float* eattr  = (const float*)d_in[2];
    const int*   batch  = (const int*)  d_in[3];
    const float* action = (const float*)d_in[4];
    const float* node_w = (const float*)d_in[5];
    const float* node_b = (const float*)d_in[6];
    const float* edge_w = (const float*)d_in[7];
    const float* edge_b = (const float*)d_in[8];
    const float* w1 = (const float*)d_in[9];  const float* b1 = (const float*)d_in[10];
    const float* g1 = (const float*)d_in[11]; const float* bb1 = (const float*)d_in[12];
    const float* w2 = (const float*)d_in[13]; const float* b2 = (const float*)d_in[14];
    const float* g2 = (const float*)d_in[15]; const float* bb2 = (const float*)d_in[16];
    const float* w3 = (const float*)d_in[17]; const float* b3 = (const float*)d_in[18];
    const float* g3 = (const float*)d_in[19]; const float* bb3 = (const float*)d_in[20];
    const float* w4 = (const float*)d_in[21]; const float* b4 = (const float*)d_in[22];
    const float* pinw = (const float*)d_in[23]; const float* pinb = (const float*)d_in[24];
    const float* phw  = (const float*)d_in[25]; const float* phb  = (const float*)d_in[26];
    const float* pow_ = (const float*)d_in[27]; const float* pob  = (const float*)d_in[28];

    const int NBLK = (Nn + 63) / 64;  // 1563

    zero_kernel<<<2048, 256>>>();                       // 1
    enc_kernel<<<NBLK, 128>>>(x, node_w, node_b);       // 2
    noop_kernel<<<1, 32>>>();                           // 3
    edge_kernel<<<2048, 256>>>(ei, eattr, edge_w, edge_b); // 4 <- ncu captures this
    stageA_kernel<<<NBLK, 256>>>(w1, b1);
    stageBC_kernel<<<NBLK, 256>>>(w2, b2, g1, bb1, 0);
    stageBC_kernel<<<NBLK, 256>>>(w3, b3, g2, bb2, 1);
    stageD_kernel<<<NBLK, 256>>>(w4, b4, g3, bb3, batch);
    head_kernel<<<1, 64>>>(action, pinw, pinb, phw, phb, pow_, pob, (float*)d_out);
}